// round 13
// baseline (speedup 1.0000x reference)
#include <cuda_runtime.h>
#include <cuda_fp16.h>
#include <cstdint>

#define NROWS 8192
#define DDIM  1024
#define MARGIN_F 0.05f
#define NEG_INF (__int_as_float(0xff800000))

#define BM 128
#define BN 128
#define BK 16                          // halves per stage -> 32B rows, 2 chunks
#define NITER (DDIM / BK)              // 64
#define NSTAGE 6
#define PFD 5                          // prefetch distance
#define NTILE_N (NROWS / BN)           // 64
#define STG_HALVES (BM * BK)           // 2048 halves = 4KB per matrix per stage
#define STG_BYTES  (STG_HALVES * 2)    // 4096

// ---------------- device scratch ----------------
__device__ __half g_xh[(size_t)NROWS * DDIM];
__device__ __half g_yh[(size_t)NROWS * DDIM];
__device__ float g_pos[NROWS];
__device__ float g_pval[(size_t)NTILE_N * NROWS];
__device__ int   g_pidx[(size_t)NTILE_N * NROWS];
__device__ float g_terms[NROWS];

// ---------------- asm helpers ----------------
__device__ __forceinline__ void cp16(uint32_t sdst, const void* gsrc) {
    asm volatile("cp.async.cg.shared.global [%0], [%1], 16;" :: "r"(sdst), "l"(gsrc) : "memory");
}
__device__ __forceinline__ void cp_commit() { asm volatile("cp.async.commit_group;" ::: "memory"); }
__device__ __forceinline__ void cp_wait4()  { asm volatile("cp.async.wait_group 4;" ::: "memory"); }
__device__ __forceinline__ void cp_wait0()  { asm volatile("cp.async.wait_group 0;" ::: "memory"); }

__device__ __forceinline__ void ldsm_x4(uint32_t& a0, uint32_t& a1, uint32_t& a2, uint32_t& a3, uint32_t addr) {
    asm volatile("ldmatrix.sync.aligned.m8n8.x4.shared.b16 {%0,%1,%2,%3}, [%4];"
        : "=r"(a0), "=r"(a1), "=r"(a2), "=r"(a3) : "r"(addr));
}
__device__ __forceinline__ void mma_f16(float* c, uint32_t a0, uint32_t a1, uint32_t a2, uint32_t a3,
                                        uint32_t b0, uint32_t b1) {
    asm volatile("mma.sync.aligned.m16n8k16.row.col.f32.f16.f16.f32 "
        "{%0,%1,%2,%3}, {%4,%5,%6,%7}, {%8,%9}, {%0,%1,%2,%3};"
        : "+f"(c[0]), "+f"(c[1]), "+f"(c[2]), "+f"(c[3])
        : "r"(a0), "r"(a1), "r"(a2), "r"(a3), "r"(b0), "r"(b1));
}

// 32B rows, 2 x 16B chunks; swizzle: c' = c ^ ((row>>2)&1)   (proven in R9/R10)
__device__ __forceinline__ uint32_t sw16(int row, int chunk) {
    return (uint32_t)(row * 32 + ((chunk ^ ((row >> 2) & 1)) << 4));
}

// ---------------- kernel 0: fused fp16 convert + exact pos_sim ----------------
__global__ void k_prep(const float* __restrict__ x, const float* __restrict__ y) {
    int row = blockIdx.x * 8 + (threadIdx.x >> 5);
    int lane = threadIdx.x & 31;
    const float4* xr = (const float4*)(x + (size_t)row * DDIM);
    const float4* yr = (const float4*)(y + (size_t)row * DDIM);
    __half2* xo = ((__half2*)g_xh) + (size_t)row * (DDIM / 2);
    __half2* yo = ((__half2*)g_yh) + (size_t)row * (DDIM / 2);
    float s = 0.f;
#pragma unroll
    for (int i = 0; i < 8; i++) {
        int j = lane + i * 32;
        float4 a = xr[j], b = yr[j];
        s += a.x * b.x + a.y * b.y + a.z * b.z + a.w * b.w;
        xo[j * 2]     = __floats2half2_rn(a.x, a.y);
        xo[j * 2 + 1] = __floats2half2_rn(a.z, a.w);
        yo[j * 2]     = __floats2half2_rn(b.x, b.y);
        yo[j * 2 + 1] = __floats2half2_rn(b.z, b.w);
    }
#pragma unroll
    for (int o = 16; o; o >>= 1) s += __shfl_xor_sync(0xffffffffu, s, o);
    if (lane == 0) g_pos[row] = s;
}

// ---------------- kernel 1: fp16 HMMA GEMM (2 CTAs/SM, 6-stage arithmetic ring) + argmax ----------------
__global__ __launch_bounds__(256, 2)
void k_gemm_mma() {
    __shared__ __align__(128) __half As[NSTAGE][STG_HALVES];   // 24 KB
    __shared__ __align__(128) __half Bs[NSTAGE][STG_HALVES];   // 24 KB (48 KB/CTA exactly)

    const int tid  = threadIdx.x;
    const int wid  = tid >> 5;
    const int lane = tid & 31;
    const int wm   = wid & 3;        // 4 warps along M (32 rows each)
    const int wn   = wid >> 2;       // 2 warps along N (64 cols each)
    const int row0 = blockIdx.x * BM;
    const int col0 = blockIdx.y * BN;

    float acc[2][8][4];
#pragma unroll
    for (int mt = 0; mt < 2; mt++)
#pragma unroll
        for (int nt = 0; nt < 8; nt++)
#pragma unroll
            for (int j = 0; j < 4; j++) acc[mt][nt][j] = 0.f;

    const int lr = tid >> 1;         // row 0..127
    const int lc = tid & 1;          // chunk 0..1

    const uint32_t sA0 = (uint32_t)__cvta_generic_to_shared(&As[0][0]);
    const uint32_t sB0 = (uint32_t)__cvta_generic_to_shared(&Bs[0][0]);
    const uint32_t aLd = sw16(lr, lc);                       // loader's fixed swizzled offset

    auto load_stage = [&](int s, int k0) {       // s used arithmetically only
        const uint32_t so = (uint32_t)s * STG_BYTES;
        cp16(sA0 + so + aLd, g_xh + (size_t)(row0 + lr) * DDIM + k0 + lc * 8);
        cp16(sB0 + so + aLd, g_yh + (size_t)(col0 + lr) * DDIM + k0 + lc * 8);
    };

#pragma unroll
    for (int s = 0; s < PFD; s++) { load_stage(s, s * BK); cp_commit(); }

    int p = 0, pf = PFD;
    for (int it = 0; it < NITER; ++it) {
        cp_wait4();                   // stage p complete; 4 groups (32 KB) in flight
        __syncthreads();              // all warps done reading stage pf (== p-1 mod 6)

        if (it + PFD < NITER) load_stage(pf, (it + PFD) * BK);
        cp_commit();

        const uint32_t so = (uint32_t)p * STG_BYTES;
        uint32_t a[2][4];
#pragma unroll
        for (int mt = 0; mt < 2; mt++) {
            int r = wm * 32 + mt * 16 + (lane & 15);
            ldsm_x4(a[mt][0], a[mt][1], a[mt][2], a[mt][3], sA0 + so + sw16(r, lane >> 4));
        }
        uint32_t b[8][2];
#pragma unroll
        for (int np = 0; np < 4; np++) {
            int r = wn * 64 + np * 16 + (lane & 15);
            uint32_t r0, r1, r2, r3;
            ldsm_x4(r0, r1, r2, r3, sB0 + so + sw16(r, lane >> 4));
            b[np * 2][0] = r0;     b[np * 2][1] = r2;      // rows n0-7
            b[np * 2 + 1][0] = r1; b[np * 2 + 1][1] = r3;  // rows n8-15
        }
#pragma unroll
        for (int mt = 0; mt < 2; mt++)
#pragma unroll
            for (int nt = 0; nt < 8; nt++)
                mma_f16(acc[mt][nt], a[mt][0], a[mt][1], a[mt][2], a[mt][3], b[nt][0], b[nt][1]);

        if (++p == NSTAGE) p = 0;
        if (++pf == NSTAGE) pf = 0;
    }
    cp_wait0();
    __syncthreads();

    // ---- epilogue: masked argmax; merge arrays alias stage 0 of As ----
    float* s_bv = (float*)&As[0][0];                       // [2][128]
    int*   s_bi = (int*)((char*)&As[0][0] + 2 * BM * 4);

#pragma unroll
    for (int mt = 0; mt < 2; mt++) {
#pragma unroll
        for (int rh = 0; rh < 2; rh++) {
            const int rloc = wm * 32 + mt * 16 + (lane >> 2) + rh * 8;
            const int row  = row0 + rloc;
            const float pos = g_pos[row];
            float bv = NEG_INF;
            int bi = 0x7fffffff;
#pragma unroll
            for (int nt = 0; nt < 8; nt++) {
#pragma unroll
                for (int j = 0; j < 2; j++) {
                    int col = col0 + wn * 64 + nt * 8 + 2 * (lane & 3) + j;
                    float s = acc[mt][nt][rh * 2 + j];
                    float v = (col == row || s > pos) ? -1.0f : s;
                    if (v > bv || (v == bv && col < bi)) { bv = v; bi = col; }
                }
            }
#pragma unroll
            for (int o = 1; o < 4; o <<= 1) {
                float ov = __shfl_xor_sync(0xffffffffu, bv, o);
                int   oi = __shfl_xor_sync(0xffffffffu, bi, o);
                if (ov > bv || (ov == bv && oi < bi)) { bv = ov; bi = oi; }
            }
            if ((lane & 3) == 0) { s_bv[wn * BM + rloc] = bv; s_bi[wn * BM + rloc] = bi; }
        }
    }
    __syncthreads();

    if (tid < BM) {
        float bv = s_bv[tid]; int bi = s_bi[tid];
        float v1 = s_bv[BM + tid]; int i1 = s_bi[BM + tid];
        if (v1 > bv || (v1 == bv && i1 < bi)) { bv = v1; bi = i1; }
        g_pval[(size_t)blockIdx.y * NROWS + row0 + tid] = bv;
        g_pidx[(size_t)blockIdx.y * NROWS + row0 + tid] = bi;
    }
}

// ---------------- kernel 2: lane-parallel merge, exact gather dot, loss term ----------------
__global__ void k_neg(const float* __restrict__ x, const float* __restrict__ y) {
    int row = blockIdx.x * 8 + (threadIdx.x >> 5);
    int lane = threadIdx.x & 31;

    float bv = g_pval[(size_t)lane * NROWS + row];
    int   bi = g_pidx[(size_t)lane * NROWS + row];
    {
        float v = g_pval[(size_t)(lane + 32) * NROWS + row];
        int   i = g_pidx[(size_t)(lane + 32) * NROWS + row];
        if (v > bv || (v == bv && i < bi)) { bv = v; bi = i; }
    }
#pragma unroll
    for (int o = 16; o; o >>= 1) {
        float ov = __shfl_xor_sync(0xffffffffu, bv, o);
        int   oi = __shfl_xor_sync(0xffffffffu, bi, o);
        if (ov > bv || (ov == bv && oi < bi)) { bv = ov; bi = oi; }
    }

    const float4* xr = (const float4*)(x + (size_t)row * DDIM);
    const float4* yr = (const float4*)(y + (size_t)bi * DDIM);
    float s = 0.f;
#pragma unroll
    for (int i = lane; i < DDIM / 4; i += 32) {
        float4 a = xr[i], b = yr[i];
        s += a.x * b.x + a.y * b.y + a.z * b.z + a.w * b.w;
    }
#pragma unroll
    for (int o = 16; o; o >>= 1) s += __shfl_xor_sync(0xffffffffu, s, o);
    if (lane == 0) g_terms[row] = fmaxf(0.f, MARGIN_F - g_pos[row] + s);
}

// ---------------- kernel 3: deterministic mean ----------------
__global__ void k_reduce(float* __restrict__ out) {
    __shared__ float sm[1024];
    int tid = threadIdx.x;
    float s = 0.f;
#pragma unroll
    for (int i = 0; i < NROWS / 1024; i++) s += g_terms[tid + i * 1024];
    sm[tid] = s;
    __syncthreads();
    for (int o = 512; o; o >>= 1) {
        if (tid < o) sm[tid] += sm[tid + o];
        __syncthreads();
    }
    if (tid == 0) out[0] = sm[0] / (float)NROWS;
}

// ---------------- launch (kernel launches ONLY) ----------------
extern "C" void kernel_launch(void* const* d_in, const int* in_sizes, int n_in,
                              void* d_out, int out_size) {
    const float* x = (const float*)d_in[0];
    const float* y = (const float*)d_in[1];
    float* out = (float*)d_out;

    k_prep<<<NROWS / 8, 256>>>(x, y);
    dim3 grid(NROWS / BM, NROWS / BN);
    k_gemm_mma<<<grid, 256>>>();
    k_neg<<<NROWS / 8, 256>>>(x, y);
    k_reduce<<<1, 1024>>>(out);
}

// round 14
// speedup vs baseline: 1.0988x; 1.0988x over previous
#include <cuda_runtime.h>
#include <cuda_fp16.h>
#include <cstdint>

#define NROWS 8192
#define DDIM  1024
#define MARGIN_F 0.05f
#define NEG_INF (__int_as_float(0xff800000))

#define BM 128
#define BN 128
#define BK 16                         // halves per stage -> 32B rows, 2 chunks
#define NITER (DDIM / BK)             // 64
#define NSTAGE 4
#define NTILE_N (NROWS / BN)          // 64
#define STG_HALVES (BM * BK)          // 2048 halves = 4KB per matrix per stage

// ---------------- device scratch ----------------
__device__ __half g_xh[(size_t)NROWS * DDIM];
__device__ __half g_yh[(size_t)NROWS * DDIM];
__device__ float g_pos[NROWS];
__device__ float g_pval[(size_t)NTILE_N * NROWS];
__device__ int   g_pidx[(size_t)NTILE_N * NROWS];
__device__ float g_terms[NROWS];

// ---------------- asm helpers ----------------
__device__ __forceinline__ void cp16(uint32_t sdst, const void* gsrc) {
    asm volatile("cp.async.cg.shared.global [%0], [%1], 16;" :: "r"(sdst), "l"(gsrc) : "memory");
}
__device__ __forceinline__ void cp_commit() { asm volatile("cp.async.commit_group;" ::: "memory"); }
__device__ __forceinline__ void cp_wait2()  { asm volatile("cp.async.wait_group 2;" ::: "memory"); }
__device__ __forceinline__ void cp_wait0()  { asm volatile("cp.async.wait_group 0;" ::: "memory"); }

__device__ __forceinline__ void ldsm_x4(uint32_t& a0, uint32_t& a1, uint32_t& a2, uint32_t& a3, uint32_t addr) {
    asm volatile("ldmatrix.sync.aligned.m8n8.x4.shared.b16 {%0,%1,%2,%3}, [%4];"
        : "=r"(a0), "=r"(a1), "=r"(a2), "=r"(a3) : "r"(addr));
}
__device__ __forceinline__ void mma_f16(float* c, uint32_t a0, uint32_t a1, uint32_t a2, uint32_t a3,
                                        uint32_t b0, uint32_t b1) {
    asm volatile("mma.sync.aligned.m16n8k16.row.col.f32.f16.f16.f32 "
        "{%0,%1,%2,%3}, {%4,%5,%6,%7}, {%8,%9}, {%0,%1,%2,%3};"
        : "+f"(c[0]), "+f"(c[1]), "+f"(c[2]), "+f"(c[3])
        : "r"(a0), "r"(a1), "r"(a2), "r"(a3), "r"(b0), "r"(b1));
}

// 32B rows, 2 x 16B chunks; swizzle: c' = c ^ ((row>>2)&1)
__device__ __forceinline__ uint32_t sw16(int row, int chunk) {
    return (uint32_t)(row * 32 + ((chunk ^ ((row >> 2) & 1)) << 4));
}

// ---------------- kernel 0: fused fp16 convert + exact pos_sim ----------------
__global__ void k_prep(const float* __restrict__ x, const float* __restrict__ y) {
    int row = blockIdx.x * 8 + (threadIdx.x >> 5);
    int lane = threadIdx.x & 31;
    const float4* xr = (const float4*)(x + (size_t)row * DDIM);
    const float4* yr = (const float4*)(y + (size_t)row * DDIM);
    __half2* xo = ((__half2*)g_xh) + (size_t)row * (DDIM / 2);
    __half2* yo = ((__half2*)g_yh) + (size_t)row * (DDIM / 2);
    float s = 0.f;
#pragma unroll
    for (int i = 0; i < 8; i++) {
        int j = lane + i * 32;
        float4 a = xr[j], b = yr[j];
        s += a.x * b.x + a.y * b.y + a.z * b.z + a.w * b.w;
        xo[j * 2]     = __floats2half2_rn(a.x, a.y);
        xo[j * 2 + 1] = __floats2half2_rn(a.z, a.w);
        yo[j * 2]     = __floats2half2_rn(b.x, b.y);
        yo[j * 2 + 1] = __floats2half2_rn(b.z, b.w);
    }
#pragma unroll
    for (int o = 16; o; o >>= 1) s += __shfl_xor_sync(0xffffffffu, s, o);
    if (lane == 0) g_pos[row] = s;
}

// ---------------- kernel 1: fp16 HMMA GEMM (2 CTAs/SM, 4-stage pipe) + fused masked argmax ----------------
// (byte-for-byte the R10 configuration — best measured: GEMM ~340us)
__global__ __launch_bounds__(256, 2)
void k_gemm_mma() {
    __shared__ __align__(128) __half As[NSTAGE][STG_HALVES];   // 16 KB
    __shared__ __align__(128) __half Bs[NSTAGE][STG_HALVES];   // 16 KB (32 KB/CTA)

    const int tid  = threadIdx.x;
    const int wid  = tid >> 5;
    const int lane = tid & 31;
    const int wm   = wid & 3;        // 4 warps along M (32 rows each)
    const int wn   = wid >> 2;       // 2 warps along N (64 cols each)
    const int row0 = blockIdx.x * BM;
    const int col0 = blockIdx.y * BN;

    float acc[2][8][4];
#pragma unroll
    for (int mt = 0; mt < 2; mt++)
#pragma unroll
        for (int nt = 0; nt < 8; nt++)
#pragma unroll
            for (int j = 0; j < 4; j++) acc[mt][nt][j] = 0.f;

    const int lr = tid >> 1;         // row 0..127
    const int lc = tid & 1;          // chunk 0..1

    uint32_t sA[NSTAGE], sB[NSTAGE];
#pragma unroll
    for (int s = 0; s < NSTAGE; s++) {
        sA[s] = (uint32_t)__cvta_generic_to_shared(&As[s][0]);
        sB[s] = (uint32_t)__cvta_generic_to_shared(&Bs[s][0]);
    }

    auto load_stage = [&](int s, int k0) {
        cp16(sA[s] + sw16(lr, lc), g_xh + (size_t)(row0 + lr) * DDIM + k0 + lc * 8);
        cp16(sB[s] + sw16(lr, lc), g_yh + (size_t)(col0 + lr) * DDIM + k0 + lc * 8);
    };

    load_stage(0, 0); cp_commit();
    load_stage(1, BK); cp_commit();
    load_stage(2, 2 * BK); cp_commit();

    for (int it = 0; it < NITER; ++it) {
        const int p = it & (NSTAGE - 1);
        cp_wait2();                   // stage p complete; 2 groups still in flight
        __syncthreads();              // all warps done with stage (it-1) == (it+3)%4

        if (it + 3 < NITER) load_stage((it + 3) & (NSTAGE - 1), (it + 3) * BK);
        cp_commit();

        // one k16 step per stage
        uint32_t a[2][4];
#pragma unroll
        for (int mt = 0; mt < 2; mt++) {
            int r = wm * 32 + mt * 16 + (lane & 15);
            ldsm_x4(a[mt][0], a[mt][1], a[mt][2], a[mt][3], sA[p] + sw16(r, lane >> 4));
        }
        uint32_t b[8][2];
#pragma unroll
        for (int np = 0; np < 4; np++) {
            int r = wn * 64 + np * 16 + (lane & 15);
            uint32_t r0, r1, r2, r3;
            ldsm_x4(r0, r1, r2, r3, sB[p] + sw16(r, lane >> 4));
            b[np * 2][0] = r0;     b[np * 2][1] = r2;
            b[np * 2 + 1][0] = r1; b[np * 2 + 1][1] = r3;
        }
#pragma unroll
        for (int mt = 0; mt < 2; mt++)
#pragma unroll
            for (int nt = 0; nt < 8; nt++)
                mma_f16(acc[mt][nt], a[mt][0], a[mt][1], a[mt][2], a[mt][3], b[nt][0], b[nt][1]);
    }
    cp_wait0();
    __syncthreads();

    // ---- epilogue: masked argmax; merge arrays alias stage 0 of As ----
    float* s_bv = (float*)&As[0][0];                       // [2][128]
    int*   s_bi = (int*)((char*)&As[0][0] + 2 * BM * 4);

#pragma unroll
    for (int mt = 0; mt < 2; mt++) {
#pragma unroll
        for (int rh = 0; rh < 2; rh++) {
            const int rloc = wm * 32 + mt * 16 + (lane >> 2) + rh * 8;
            const int row  = row0 + rloc;
            const float pos = g_pos[row];
            float bv = NEG_INF;
            int bi = 0x7fffffff;
#pragma unroll
            for (int nt = 0; nt < 8; nt++) {
#pragma unroll
                for (int j = 0; j < 2; j++) {
                    int col = col0 + wn * 64 + nt * 8 + 2 * (lane & 3) + j;
                    float s = acc[mt][nt][rh * 2 + j];
                    float v = (col == row || s > pos) ? -1.0f : s;
                    if (v > bv || (v == bv && col < bi)) { bv = v; bi = col; }
                }
            }
#pragma unroll
            for (int o = 1; o < 4; o <<= 1) {
                float ov = __shfl_xor_sync(0xffffffffu, bv, o);
                int   oi = __shfl_xor_sync(0xffffffffu, bi, o);
                if (ov > bv || (ov == bv && oi < bi)) { bv = ov; bi = oi; }
            }
            if ((lane & 3) == 0) { s_bv[wn * BM + rloc] = bv; s_bi[wn * BM + rloc] = bi; }
        }
    }
    __syncthreads();

    if (tid < BM) {
        float bv = s_bv[tid]; int bi = s_bi[tid];
        float v1 = s_bv[BM + tid]; int i1 = s_bi[BM + tid];
        if (v1 > bv || (v1 == bv && i1 < bi)) { bv = v1; bi = i1; }
        g_pval[(size_t)blockIdx.y * NROWS + row0 + tid] = bv;
        g_pidx[(size_t)blockIdx.y * NROWS + row0 + tid] = bi;
    }
}

// ---------------- kernel 2: lane-parallel merge, fp16-input gather dot (fp32 accum), loss ----------------
__global__ void k_neg() {
    int row = blockIdx.x * 8 + (threadIdx.x >> 5);
    int lane = threadIdx.x & 31;

    float bv = g_pval[(size_t)lane * NROWS + row];
    int   bi = g_pidx[(size_t)lane * NROWS + row];
    {
        float v = g_pval[(size_t)(lane + 32) * NROWS + row];
        int   i = g_pidx[(size_t)(lane + 32) * NROWS + row];
        if (v > bv || (v == bv && i < bi)) { bv = v; bi = i; }
    }
#pragma unroll
    for (int o = 16; o; o >>= 1) {
        float ov = __shfl_xor_sync(0xffffffffu, bv, o);
        int   oi = __shfl_xor_sync(0xffffffffu, bi, o);
        if (ov > bv || (ov == bv && oi < bi)) { bv = ov; bi = oi; }
    }

    // gather dot on fp16 operands, fp32 accumulate (halves traffic; error ~3e-5/row, zero-mean)
    const uint4* xr = (const uint4*)(g_xh + (size_t)row * DDIM);
    const uint4* yr = (const uint4*)(g_yh + (size_t)bi * DDIM);
    float s = 0.f;
#pragma unroll
    for (int i = 0; i < 4; i++) {
        uint4 av = xr[lane + i * 32];
        uint4 bv4 = yr[lane + i * 32];
        const __half2* ah = (const __half2*)&av;
        const __half2* bh = (const __half2*)&bv4;
#pragma unroll
        for (int j = 0; j < 4; j++) {
            float2 a2 = __half22float2(ah[j]);
            float2 b2 = __half22float2(bh[j]);
            s += a2.x * b2.x + a2.y * b2.y;
        }
    }
#pragma unroll
    for (int o = 16; o; o >>= 1) s += __shfl_xor_sync(0xffffffffu, s, o);
    if (lane == 0) g_terms[row] = fmaxf(0.f, MARGIN_F - g_pos[row] + s);
}

// ---------------- kernel 3: deterministic mean ----------------
__global__ void k_reduce(float* __restrict__ out) {
    __shared__ float sm[1024];
    int tid = threadIdx.x;
    float s = 0.f;
#pragma unroll
    for (int i = 0; i < NROWS / 1024; i++) s += g_terms[tid + i * 1024];
    sm[tid] = s;
    __syncthreads();
    for (int o = 512; o; o >>= 1) {
        if (tid < o) sm[tid] += sm[tid + o];
        __syncthreads();
    }
    if (tid == 0) out[0] = sm[0] / (float)NROWS;
}

// ---------------- launch (kernel launches ONLY) ----------------
extern "C" void kernel_launch(void* const* d_in, const int* in_sizes, int n_in,
                              void* d_out, int out_size) {
    const float* x = (const float*)d_in[0];
    const float* y = (const float*)d_in[1];
    float* out = (float*)d_out;

    k_prep<<<NROWS / 8, 256>>>(x, y);
    dim3 grid(NROWS / BM, NROWS / BN);
    k_gemm_mma<<<grid, 256>>>();
    k_neg<<<NROWS / 8, 256>>>();
    k_reduce<<<1, 1024>>>(out);
}

// round 15
// speedup vs baseline: 1.0995x; 1.0006x over previous
#include <cuda_runtime.h>
#include <cuda_fp16.h>
#include <cstdint>

#define NROWS 8192
#define DDIM  1024
#define MARGIN_F 0.05f
#define NEG_INF (__int_as_float(0xff800000))

#define BM 128
#define BN 128
#define BK 16                         // halves per stage -> 32B rows, 2 chunks
#define NITER (DDIM / BK)             // 64
#define NSTAGE 4
#define NTILE_N (NROWS / BN)          // 64
#define STG_HALVES (BM * BK)          // 2048 halves = 4KB per matrix per stage

// ---------------- device scratch ----------------
__device__ __half g_xh[(size_t)NROWS * DDIM];
__device__ __half g_yh[(size_t)NROWS * DDIM];
__device__ float g_pos2[2 * NROWS];               // half-row pos partials
__device__ float g_pval[(size_t)NTILE_N * NROWS];
__device__ int   g_pidx[(size_t)NTILE_N * NROWS];
__device__ float g_terms[NROWS];

// ---------------- asm helpers ----------------
__device__ __forceinline__ void cp16(uint32_t sdst, const void* gsrc) {
    asm volatile("cp.async.cg.shared.global [%0], [%1], 16;" :: "r"(sdst), "l"(gsrc) : "memory");
}
__device__ __forceinline__ void cp_commit() { asm volatile("cp.async.commit_group;" ::: "memory"); }
__device__ __forceinline__ void cp_wait2()  { asm volatile("cp.async.wait_group 2;" ::: "memory"); }
__device__ __forceinline__ void cp_wait0()  { asm volatile("cp.async.wait_group 0;" ::: "memory"); }

__device__ __forceinline__ void ldsm_x4(uint32_t& a0, uint32_t& a1, uint32_t& a2, uint32_t& a3, uint32_t addr) {
    asm volatile("ldmatrix.sync.aligned.m8n8.x4.shared.b16 {%0,%1,%2,%3}, [%4];"
        : "=r"(a0), "=r"(a1), "=r"(a2), "=r"(a3) : "r"(addr));
}
__device__ __forceinline__ void mma_f16(float* c, uint32_t a0, uint32_t a1, uint32_t a2, uint32_t a3,
                                        uint32_t b0, uint32_t b1) {
    asm volatile("mma.sync.aligned.m16n8k16.row.col.f32.f16.f16.f32 "
        "{%0,%1,%2,%3}, {%4,%5,%6,%7}, {%8,%9}, {%0,%1,%2,%3};"
        : "+f"(c[0]), "+f"(c[1]), "+f"(c[2]), "+f"(c[3])
        : "r"(a0), "r"(a1), "r"(a2), "r"(a3), "r"(b0), "r"(b1));
}

// 32B rows, 2 x 16B chunks; swizzle: c' = c ^ ((row>>2)&1)
__device__ __forceinline__ uint32_t sw16(int row, int chunk) {
    return (uint32_t)(row * 32 + ((chunk ^ ((row >> 2) & 1)) << 4));
}

// ---------------- kernel 0: fp16 convert + pos partials (warp per HALF row) ----------------
__global__ void k_prep(const float* __restrict__ x, const float* __restrict__ y) {
    int wglob = blockIdx.x * 8 + (threadIdx.x >> 5);   // 0 .. 2*NROWS-1
    int row  = wglob >> 1;
    int half = wglob & 1;
    int lane = threadIdx.x & 31;

    const float4* xr = (const float4*)(x + (size_t)row * DDIM) + half * 128;
    const float4* yr = (const float4*)(y + (size_t)row * DDIM) + half * 128;
    __half2* xo = ((__half2*)g_xh) + (size_t)row * (DDIM / 2) + half * 256;
    __half2* yo = ((__half2*)g_yh) + (size_t)row * (DDIM / 2) + half * 256;

    float s = 0.f;
#pragma unroll
    for (int i = 0; i < 4; i++) {
        int j = lane + i * 32;
        float4 a = xr[j], b = yr[j];
        s += a.x * b.x + a.y * b.y + a.z * b.z + a.w * b.w;
        xo[j * 2]     = __floats2half2_rn(a.x, a.y);
        xo[j * 2 + 1] = __floats2half2_rn(a.z, a.w);
        yo[j * 2]     = __floats2half2_rn(b.x, b.y);
        yo[j * 2 + 1] = __floats2half2_rn(b.z, b.w);
    }
#pragma unroll
    for (int o = 16; o; o >>= 1) s += __shfl_xor_sync(0xffffffffu, s, o);
    if (lane == 0) g_pos2[half * NROWS + row] = s;
}

// ---------------- kernel 1: fp16 HMMA GEMM (2 CTAs/SM, 4-stage pipe) + fused masked argmax ----------------
__global__ __launch_bounds__(256, 2)
void k_gemm_mma() {
    __shared__ __align__(128) __half As[NSTAGE][STG_HALVES];   // 16 KB
    __shared__ __align__(128) __half Bs[NSTAGE][STG_HALVES];   // 16 KB (32 KB/CTA)

    const int tid  = threadIdx.x;
    const int wid  = tid >> 5;
    const int lane = tid & 31;
    const int wm   = wid & 3;        // 4 warps along M (32 rows each)
    const int wn   = wid >> 2;       // 2 warps along N (64 cols each)
    const int row0 = blockIdx.x * BM;
    const int col0 = blockIdx.y * BN;

    float acc[2][8][4];
#pragma unroll
    for (int mt = 0; mt < 2; mt++)
#pragma unroll
        for (int nt = 0; nt < 8; nt++)
#pragma unroll
            for (int j = 0; j < 4; j++) acc[mt][nt][j] = 0.f;

    const int lr = tid >> 1;         // row 0..127
    const int lc = tid & 1;          // chunk 0..1

    uint32_t sA[NSTAGE], sB[NSTAGE];
#pragma unroll
    for (int s = 0; s < NSTAGE; s++) {
        sA[s] = (uint32_t)__cvta_generic_to_shared(&As[s][0]);
        sB[s] = (uint32_t)__cvta_generic_to_shared(&Bs[s][0]);
    }

    auto load_stage = [&](int s, int k0) {
        cp16(sA[s] + sw16(lr, lc), g_xh + (size_t)(row0 + lr) * DDIM + k0 + lc * 8);
        cp16(sB[s] + sw16(lr, lc), g_yh + (size_t)(col0 + lr) * DDIM + k0 + lc * 8);
    };

    load_stage(0, 0); cp_commit();
    load_stage(1, BK); cp_commit();
    load_stage(2, 2 * BK); cp_commit();

    for (int it = 0; it < NITER; ++it) {
        const int p = it & (NSTAGE - 1);
        cp_wait2();                   // stage p complete; 2 groups still in flight
        __syncthreads();              // all warps done with stage (it-1) == (it+3)%4

        if (it + 3 < NITER) load_stage((it + 3) & (NSTAGE - 1), (it + 3) * BK);
        cp_commit();

        // one k16 step per stage
        uint32_t a[2][4];
#pragma unroll
        for (int mt = 0; mt < 2; mt++) {
            int r = wm * 32 + mt * 16 + (lane & 15);
            ldsm_x4(a[mt][0], a[mt][1], a[mt][2], a[mt][3], sA[p] + sw16(r, lane >> 4));
        }
        uint32_t b[8][2];
#pragma unroll
        for (int np = 0; np < 4; np++) {
            int r = wn * 64 + np * 16 + (lane & 15);
            uint32_t r0, r1, r2, r3;
            ldsm_x4(r0, r1, r2, r3, sB[p] + sw16(r, lane >> 4));
            b[np * 2][0] = r0;     b[np * 2][1] = r2;
            b[np * 2 + 1][0] = r1; b[np * 2 + 1][1] = r3;
        }
#pragma unroll
        for (int mt = 0; mt < 2; mt++)
#pragma unroll
            for (int nt = 0; nt < 8; nt++)
                mma_f16(acc[mt][nt], a[mt][0], a[mt][1], a[mt][2], a[mt][3], b[nt][0], b[nt][1]);
    }
    cp_wait0();
    __syncthreads();

    // ---- epilogue: masked argmax; merge arrays alias stage 0 of As ----
    float* s_bv = (float*)&As[0][0];                       // [2][128]
    int*   s_bi = (int*)((char*)&As[0][0] + 2 * BM * 4);

#pragma unroll
    for (int mt = 0; mt < 2; mt++) {
#pragma unroll
        for (int rh = 0; rh < 2; rh++) {
            const int rloc = wm * 32 + mt * 16 + (lane >> 2) + rh * 8;
            const int row  = row0 + rloc;
            const float pos = g_pos2[row] + g_pos2[NROWS + row];
            float bv = NEG_INF;
            int bi = 0x7fffffff;
#pragma unroll
            for (int nt = 0; nt < 8; nt++) {
#pragma unroll
                for (int j = 0; j < 2; j++) {
                    int col = col0 + wn * 64 + nt * 8 + 2 * (lane & 3) + j;
                    float s = acc[mt][nt][rh * 2 + j];
                    float v = (col == row || s > pos) ? -1.0f : s;
                    if (v > bv || (v == bv && col < bi)) { bv = v; bi = col; }
                }
            }
#pragma unroll
            for (int o = 1; o < 4; o <<= 1) {
                float ov = __shfl_xor_sync(0xffffffffu, bv, o);
                int   oi = __shfl_xor_sync(0xffffffffu, bi, o);
                if (ov > bv || (ov == bv && oi < bi)) { bv = ov; bi = oi; }
            }
            if ((lane & 3) == 0) { s_bv[wn * BM + rloc] = bv; s_bi[wn * BM + rloc] = bi; }
        }
    }
    __syncthreads();

    if (tid < BM) {
        float bv = s_bv[tid]; int bi = s_bi[tid];
        float v1 = s_bv[BM + tid]; int i1 = s_bi[BM + tid];
        if (v1 > bv || (v1 == bv && i1 < bi)) { bv = v1; bi = i1; }
        g_pval[(size_t)blockIdx.y * NROWS + row0 + tid] = bv;
        g_pidx[(size_t)blockIdx.y * NROWS + row0 + tid] = bi;
    }
}

// ---------------- kernel 2: lane-parallel merge, fp16-input gather dot (fp32 accum), loss ----------------
__global__ void k_neg() {
    int row = blockIdx.x * 8 + (threadIdx.x >> 5);
    int lane = threadIdx.x & 31;

    float bv = g_pval[(size_t)lane * NROWS + row];
    int   bi = g_pidx[(size_t)lane * NROWS + row];
    {
        float v = g_pval[(size_t)(lane + 32) * NROWS + row];
        int   i = g_pidx[(size_t)(lane + 32) * NROWS + row];
        if (v > bv || (v == bv && i < bi)) { bv = v; bi = i; }
    }
#pragma unroll
    for (int o = 16; o; o >>= 1) {
        float ov = __shfl_xor_sync(0xffffffffu, bv, o);
        int   oi = __shfl_xor_sync(0xffffffffu, bi, o);
        if (ov > bv || (ov == bv && oi < bi)) { bv = ov; bi = oi; }
    }

    // gather dot on fp16 operands, fp32 accumulate
    const uint4* xr = (const uint4*)(g_xh + (size_t)row * DDIM);
    const uint4* yr = (const uint4*)(g_yh + (size_t)bi * DDIM);
    float s = 0.f;
#pragma unroll
    for (int i = 0; i < 4; i++) {
        uint4 av = xr[lane + i * 32];
        uint4 bv4 = yr[lane + i * 32];
        const __half2* ah = (const __half2*)&av;
        const __half2* bh = (const __half2*)&bv4;
#pragma unroll
        for (int j = 0; j < 4; j++) {
            float2 a2 = __half22float2(ah[j]);
            float2 b2 = __half22float2(bh[j]);
            s += a2.x * b2.x + a2.y * b2.y;
        }
    }
#pragma unroll
    for (int o = 16; o; o >>= 1) s += __shfl_xor_sync(0xffffffffu, s, o);
    if (lane == 0) {
        float pos = g_pos2[row] + g_pos2[NROWS + row];
        g_terms[row] = fmaxf(0.f, MARGIN_F - pos + s);
    }
}

// ---------------- kernel 3: deterministic mean ----------------
__global__ void k_reduce(float* __restrict__ out) {
    __shared__ float sm[1024];
    int tid = threadIdx.x;
    float s = 0.f;
#pragma unroll
    for (int i = 0; i < NROWS / 1024; i++) s += g_terms[tid + i * 1024];
    sm[tid] = s;
    __syncthreads();
    for (int o = 512; o; o >>= 1) {
        if (tid < o) sm[tid] += sm[tid + o];
        __syncthreads();
    }
    if (tid == 0) out[0] = sm[0] / (float)NROWS;
}

// ---------------- launch (kernel launches ONLY) ----------------
extern "C" void kernel_launch(void* const* d_in, const int* in_sizes, int n_in,
                              void* d_out, int out_size) {
    const float* x = (const float*)d_in[0];
    const float* y = (const float*)d_in[1];
    float* out = (float*)d_out;

    k_prep<<<2 * NROWS / 8, 256>>>(x, y);
    dim3 grid(NROWS / BM, NROWS / BN);
    k_gemm_mma<<<grid, 256>>>();
    k_neg<<<NROWS / 8, 256>>>();
    k_reduce<<<1, 1024>>>(out);
}